// round 1
// baseline (speedup 1.0000x reference)
#include <cuda_runtime.h>
#include <cstdint>

// Problem constants (fixed by the dataset)
#define NCLS   13
#define PD     128     // prior dim
#define BM     64      // points per block
#define NTHR   256
#define MINPTS 256.0f

// ---------------- device scratch (no allocs allowed) ----------------
__device__ float g_sums[NCLS * PD];
__device__ int   g_counts[NCLS];

// ---------------- kernel 0: zero scratch ----------------
__global__ void zero_kernel() {
    int i = blockIdx.x * blockDim.x + threadIdx.x;
    if (i < NCLS * PD) g_sums[i] = 0.f;
    if (i < NCLS) g_counts[i] = 0;
}

// ---------------- kernel 1: per-class counts ----------------
__global__ void count_kernel(const int* __restrict__ y, int P) {
    __shared__ int sc[NCLS];
    if (threadIdx.x < NCLS) sc[threadIdx.x] = 0;
    __syncthreads();
    for (int i = blockIdx.x * blockDim.x + threadIdx.x; i < P;
         i += gridDim.x * blockDim.x) {
        atomicAdd(&sc[y[i]], 1);
    }
    __syncthreads();
    if (threadIdx.x < NCLS) atomicAdd(&g_counts[threadIdx.x], sc[threadIdx.x]);
}

// ---------------- fused GEMM layer (K%16==0) ----------------
// A: shared col-major [K][64].  W: global row-major [K][N].
// RM=false: C shared col-major [N][64].  RM=true: C shared row-major stride 132.
template <int K, int N, bool RM>
__device__ __forceinline__ void gemm_relu(
    const float* __restrict__ Wg, const float* __restrict__ bg,
    const float* __restrict__ Ash, float* __restrict__ Csh,
    float* __restrict__ Wsh, int tid)
{
    const int tx = tid & 15;      // n-group
    const int ty = tid >> 4;      // m-group
    const int m0 = ty << 2;
    #pragma unroll
    for (int nT = 0; nT < N / 64; nT++) {
        float acc[4][4] = {};
        for (int kT = 0; kT < K / 16; kT++) {
            // stage W tile [16][64] (coalesced float4)
            float4 w4 = *(const float4*)&Wg[(size_t)(kT * 16 + ty) * N + nT * 64 + (tx << 2)];
            __syncthreads();                        // prior readers of Wsh done
            *(float4*)&Wsh[(ty << 6) + (tx << 2)] = w4;
            __syncthreads();
            #pragma unroll
            for (int kk = 0; kk < 16; kk++) {
                float4 a4 = *(const float4*)&Ash[(kT * 16 + kk) * 64 + m0];
                float4 w  = *(const float4*)&Wsh[(kk << 6) + (tx << 2)];
                float av[4] = {a4.x, a4.y, a4.z, a4.w};
                float wv[4] = {w.x,  w.y,  w.z,  w.w};
                #pragma unroll
                for (int i = 0; i < 4; i++)
                    #pragma unroll
                    for (int j = 0; j < 4; j++)
                        acc[i][j] += av[i] * wv[j];
            }
        }
        // epilogue: bias + relu + store
        if (!RM) {
            #pragma unroll
            for (int j = 0; j < 4; j++) {
                int n = nT * 64 + (tx << 2) + j;
                float b = bg[n];
                float4 v;
                v.x = fmaxf(acc[0][j] + b, 0.f);
                v.y = fmaxf(acc[1][j] + b, 0.f);
                v.z = fmaxf(acc[2][j] + b, 0.f);
                v.w = fmaxf(acc[3][j] + b, 0.f);
                *(float4*)&Csh[n * 64 + m0] = v;
            }
        } else {
            int n0g = nT * 64 + (tx << 2);
            float b0 = bg[n0g], b1 = bg[n0g + 1], b2 = bg[n0g + 2], b3 = bg[n0g + 3];
            #pragma unroll
            for (int i = 0; i < 4; i++) {
                float4 v;
                v.x = fmaxf(acc[i][0] + b0, 0.f);
                v.y = fmaxf(acc[i][1] + b1, 0.f);
                v.z = fmaxf(acc[i][2] + b2, 0.f);
                v.w = fmaxf(acc[i][3] + b3, 0.f);
                *(float4*)&Csh[(m0 + i) * 132 + n0g] = v;
            }
        }
    }
}

// ---------------- layer 1 (K=7, N=256) ----------------
__device__ __forceinline__ void layer1(
    const float* __restrict__ Wg, const float* __restrict__ bg,
    const float* __restrict__ Ish, float* __restrict__ Csh,
    float* __restrict__ Wsh, int tid)
{
    const int tx = tid & 15;
    const int ty = tid >> 4;
    const int m0 = ty << 2;
    #pragma unroll
    for (int nT = 0; nT < 4; nT++) {
        float acc[4][4] = {};
        float4 w4 = make_float4(0.f, 0.f, 0.f, 0.f);
        bool ld = (ty < 7);
        if (ld) w4 = *(const float4*)&Wg[ty * 256 + nT * 64 + (tx << 2)];
        __syncthreads();
        if (ld) *(float4*)&Wsh[(ty << 6) + (tx << 2)] = w4;
        __syncthreads();
        #pragma unroll
        for (int kk = 0; kk < 7; kk++) {
            float4 a4 = *(const float4*)&Ish[kk * 64 + m0];
            float4 w  = *(const float4*)&Wsh[(kk << 6) + (tx << 2)];
            float av[4] = {a4.x, a4.y, a4.z, a4.w};
            float wv[4] = {w.x,  w.y,  w.z,  w.w};
            #pragma unroll
            for (int i = 0; i < 4; i++)
                #pragma unroll
                for (int j = 0; j < 4; j++)
                    acc[i][j] += av[i] * wv[j];
        }
        #pragma unroll
        for (int j = 0; j < 4; j++) {
            int n = nT * 64 + (tx << 2) + j;
            float b = bg[n];
            float4 v;
            v.x = fmaxf(acc[0][j] + b, 0.f);
            v.y = fmaxf(acc[1][j] + b, 0.f);
            v.z = fmaxf(acc[2][j] + b, 0.f);
            v.w = fmaxf(acc[3][j] + b, 0.f);
            *(float4*)&Csh[n * 64 + m0] = v;
        }
    }
}

// ---------------- kernel 2: fused MLP + normalize + sums + current_prior ----------------
// shared layout (floats):
//   bufB  [512][64] = 32768     (also overlaid as bufF [64][132] = 8448 for final feat)
//   bufA  [256][64] = 16384
//   bufI  [  8][64] =   512
//   Wsh   [ 16][64] =  1024
//   sSum  [2][13][128] = 3328
//   sInv  [64], sLbl [64] (float), sLab [64] (int)
#define SMEM_FLOATS (32768 + 16384 + 512 + 1024 + 3328 + 64 + 64 + 64)

__global__ __launch_bounds__(NTHR, 1)
void mlp_kernel(const float* __restrict__ pos, const float* __restrict__ x,
                const int* __restrict__ y,
                const float* __restrict__ We1, const float* __restrict__ be1,
                const float* __restrict__ We2, const float* __restrict__ be2,
                const float* __restrict__ W1,  const float* __restrict__ b1,
                const float* __restrict__ W2,  const float* __restrict__ b2,
                float* __restrict__ out, int P, int Npts)
{
    extern __shared__ float sm[];
    float* bufB = sm;                  // 32768
    float* bufA = bufB + 32768;        // 16384
    float* bufI = bufA + 16384;        // 512
    float* Wsh  = bufI + 512;          // 1024
    float* sSum = Wsh + 1024;          // 3328
    float* sInv = sSum + 3328;         // 64
    float* sLbl = sInv + 64;           // 64
    int*   sLab = (int*)(sLbl + 64);   // 64
    float* bufF = bufB;                // overlay [64][132]

    const int tid  = threadIdx.x;
    const int base = blockIdx.x * BM;

    // ---- load inputs (col-major [8][64]: k<4 features from x, 4..6 coords) ----
    for (int i = tid; i < BM * 8; i += NTHR) {
        int m = i & 63, k = i >> 6;
        int p = base + m;
        float v = 0.f;
        if (p < P && k < 7) {
            int b = p / Npts, n = p - b * Npts;
            if (k < 4) v = x[((size_t)b * 4 + k) * Npts + n];
            else       v = pos[(size_t)p * 3 + (k - 4)];
        }
        bufI[i] = v;
    }
    if (tid < BM) {
        int p = base + tid;
        int l = (p < P) ? y[p] : 0;
        sLab[tid] = l;
        float cnt = (float)g_counts[l];
        sLbl[tid] = (cnt >= MINPTS) ? (float)l : -1.f;
    }
    for (int i = tid; i < 2 * NCLS * PD; i += NTHR) sSum[i] = 0.f;
    __syncthreads();

    // ---- MLP chain ----
    layer1(We1, be1, bufI, bufA, Wsh, tid);                 //   7 -> 256 (bufA)
    gemm_relu<256, 512, false>(We2, be2, bufA, bufB, Wsh, tid); // 256 -> 512 (bufB)
    gemm_relu<512, 256, false>(W1,  b1,  bufB, bufA, Wsh, tid); // 512 -> 256 (bufA)
    gemm_relu<256, 128, true >(W2,  b2,  bufA, bufF, Wsh, tid); // 256 -> 128 (bufF rm, stride 132)
    __syncthreads();

    // ---- L2 norms ----
    if (tid < BM) {
        float s = 0.f;
        const float4* r = (const float4*)(bufF + tid * 132);
        #pragma unroll
        for (int j = 0; j < 32; j++) {
            float4 q = r[j];
            s += q.x * q.x + q.y * q.y + q.z * q.z + q.w * q.w;
        }
        sInv[tid] = 1.f / fmaxf(sqrtf(s), 1e-12f);
    }
    __syncthreads();

    // ---- per-class sums (2 race-free shared copies) ----
    {
        int n = tid & 127, half = tid >> 7;
        float* dst = sSum + half * NCLS * PD + n;
        for (int mm = 0; mm < 32; mm++) {
            int m = (half << 5) + mm;
            if (base + m < P) {
                int l = sLab[m];
                dst[l * PD] += bufF[m * 132 + n] * sInv[m];
            }
        }
    }
    __syncthreads();
    for (int i = tid; i < NCLS * PD; i += NTHR)
        atomicAdd(&g_sums[i], sSum[i] + sSum[NCLS * PD + i]);

    // ---- write current_prior rows [64][129] ----
    size_t gbase = (size_t)base * 129;
    for (int i = tid; i < BM * 129; i += NTHR) {
        int m = i / 129, c = i - m * 129;
        if (base + m < P)
            out[gbase + i] = (c < PD) ? bufF[m * 132 + c] * sInv[m] : sLbl[m];
    }
}

// ---------------- kernel 3: EMA prior update ----------------
__global__ void prior_kernel(const float* __restrict__ prior, float* __restrict__ out, int P) {
    __shared__ float red[4];
    int n = threadIdx.x;           // 0..127
    int lane = n & 31, w = n >> 5;
    for (int cls = 0; cls < NCLS; cls++) {
        float cnt = (float)g_counts[cls];
        bool valid = (cnt >= MINPTS);
        float mean = g_sums[cls * PD + n] / fmaxf(cnt, 1.f);
        float pe   = prior[cls * PD + n];
        float cur  = valid ? mean : pe;
        float v    = 0.999f * pe + 0.001f * cur;
        float s = v * v;
        #pragma unroll
        for (int o = 16; o > 0; o >>= 1) s += __shfl_xor_sync(0xffffffffu, s, o);
        if (lane == 0) red[w] = s;
        __syncthreads();
        float tot = red[0] + red[1] + red[2] + red[3];
        out[(size_t)P * 129 + cls * PD + n] = v / fmaxf(sqrtf(tot), 1e-12f);
        __syncthreads();
    }
}

// ---------------- launch ----------------
extern "C" void kernel_launch(void* const* d_in, const int* in_sizes, int n_in,
                              void* d_out, int out_size)
{
    const float* pos = (const float*)d_in[0];
    const float* x   = (const float*)d_in[1];
    const int*   y   = (const int*)  d_in[2];
    const float* We1 = (const float*)d_in[3];
    const float* be1 = (const float*)d_in[4];
    const float* We2 = (const float*)d_in[5];
    const float* be2 = (const float*)d_in[6];
    const float* W1  = (const float*)d_in[7];
    const float* b1  = (const float*)d_in[8];
    const float* W2  = (const float*)d_in[9];
    const float* b2  = (const float*)d_in[10];
    const float* pe  = (const float*)d_in[11];
    float* out = (float*)d_out;

    int P    = in_sizes[2];                 // 160000 points
    int B    = in_sizes[0] / 3 / 40000;     // batch (pos = B*N*3)
    int Npts = (B > 0) ? (in_sizes[0] / 3 / B) : 40000;

    size_t smem = SMEM_FLOATS * sizeof(float);
    cudaFuncSetAttribute(mlp_kernel, cudaFuncAttributeMaxDynamicSharedMemorySize, (int)smem);

    zero_kernel<<<7, 256>>>();
    count_kernel<<<(P + 255) / 256, 256>>>(y, P);
    mlp_kernel<<<(P + BM - 1) / BM, NTHR, smem>>>(pos, x, y, We1, be1, We2, be2,
                                                  W1, b1, W2, b2, out, P, Npts);
    prior_kernel<<<1, 128>>>(pe, out, P);
}

// round 2
// speedup vs baseline: 4.9283x; 4.9283x over previous
#include <cuda_runtime.h>
#include <cstdint>

#define NCLS   13
#define PD     128
#define BM     64
#define NTHR   256
#define MINPTS 256.0f

// packed tf32 weight offsets (K padded to mult of 8)
#define OFF1 0
#define OFF2 2048                 //  8*256
#define OFF3 (OFF2 + 131072)      //  256*512
#define OFF4 (OFF3 + 131072)      //  512*256
#define WPTOT (OFF4 + 32768)      //  256*128

__device__ float g_wp[WPTOT];
__device__ float g_sums[NCLS * PD];
__device__ int   g_counts[NCLS];

__device__ __forceinline__ float tf32r(float x) {
    uint32_t u;
    asm("cvt.rna.tf32.f32 %0, %1;" : "=r"(u) : "f"(x));
    return __uint_as_float(u);
}

__device__ __forceinline__ void mma_tf32(float* c, uint32_t a0, uint32_t a1,
                                         uint32_t a2, uint32_t a3,
                                         uint32_t b0, uint32_t b1) {
    asm volatile(
        "mma.sync.aligned.m16n8k8.row.col.f32.tf32.tf32.f32 "
        "{%0,%1,%2,%3}, {%4,%5,%6,%7}, {%8,%9}, {%0,%1,%2,%3};\n"
        : "+f"(c[0]), "+f"(c[1]), "+f"(c[2]), "+f"(c[3])
        : "r"(a0), "r"(a1), "r"(a2), "r"(a3), "r"(b0), "r"(b1));
}

// storage slot permutation within 8-col group: (k, k+4) become adjacent
__device__ __forceinline__ int slot8(int c) {
    return (c & ~7) | (((c & 3) << 1) | ((c & 7) >> 2));
}

// ---------------- kernel 0: zero scratch ----------------
__global__ void zero_kernel() {
    int i = blockIdx.x * blockDim.x + threadIdx.x;
    if (i < NCLS * PD) g_sums[i] = 0.f;
    if (i < NCLS) g_counts[i] = 0;
}

// ---------------- kernel 1: per-class counts ----------------
__global__ void count_kernel(const int* __restrict__ y, int P) {
    __shared__ int sc[NCLS];
    if (threadIdx.x < NCLS) sc[threadIdx.x] = 0;
    __syncthreads();
    for (int i = blockIdx.x * blockDim.x + threadIdx.x; i < P;
         i += gridDim.x * blockDim.x)
        atomicAdd(&sc[y[i]], 1);
    __syncthreads();
    if (threadIdx.x < NCLS) atomicAdd(&g_counts[threadIdx.x], sc[threadIdx.x]);
}

// ---------------- kernel 1b: pack weights to tf32 fragment order ----------------
// dst[p]: p = ((j*(K/8)+kc)*32 + lane)*2 + t ; k = kc*8 + (lane&3) + 4t ; n = j*8 + lane/4
__global__ void pack_kernel(const float* __restrict__ src, int dstOff,
                            int K, int N, int Ksrc) {
    int p = blockIdx.x * blockDim.x + threadIdx.x;
    if (p >= K * N) return;
    int t = p & 1, l = (p >> 1) & 31;
    int rest = p >> 6;
    int kc = rest % (K >> 3);
    int j  = rest / (K >> 3);
    int k = kc * 8 + (l & 3) + 4 * t;
    int n = j * 8 + (l >> 2);
    float v = (k < Ksrc) ? src[k * N + n] : 0.f;
    g_wp[dstOff + p] = tf32r(v);
}

// ---------------- tf32 mma layer ----------------
// A in shared: row-major [64][ASTR], permuted 8-col groups, tf32-rounded values.
// W packed in g_wp (fragment order). Output: permuted groups unless LASTL
// (then plain row-major stride CSTR, no tf32 rounding).
template <int K, int N, int ASTR, int CSTR, int NT, bool LASTL>
__device__ __forceinline__ void mma_layer(
    const float* __restrict__ Wp, const float* __restrict__ bias,
    const float* __restrict__ Ash, float* __restrict__ Csh,
    int warp, int lane)
{
    const int r = lane & 3, q = lane >> 2;
    constexpr int SLICE = N / 8;            // columns per warp
    constexpr int NCH = SLICE / (NT * 8);
    #pragma unroll
    for (int ch = 0; ch < NCH; ch++) {
        const int nbase = warp * SLICE + ch * NT * 8;
        float acc[4][NT][4];
        #pragma unroll
        for (int mt = 0; mt < 4; mt++)
            #pragma unroll
            for (int nt = 0; nt < NT; nt++)
                #pragma unroll
                for (int i = 0; i < 4; i++) acc[mt][nt][i] = 0.f;

        #pragma unroll 4
        for (int kc = 0; kc < K / 8; kc++) {
            uint2 a[4][2];
            #pragma unroll
            for (int mt = 0; mt < 4; mt++) {
                a[mt][0] = *(const uint2*)&Ash[(mt * 16 + q)     * ASTR + kc * 8 + r * 2];
                a[mt][1] = *(const uint2*)&Ash[(mt * 16 + q + 8) * ASTR + kc * 8 + r * 2];
            }
            uint2 b[NT];
            #pragma unroll
            for (int nt = 0; nt < NT; nt++) {
                int j = (nbase >> 3) + nt;
                b[nt] = *(const uint2*)&Wp[(size_t)((j * (K / 8) + kc) * 32 + lane) * 2];
            }
            #pragma unroll
            for (int mt = 0; mt < 4; mt++)
                #pragma unroll
                for (int nt = 0; nt < NT; nt++)
                    mma_tf32(acc[mt][nt], a[mt][0].x, a[mt][1].x,
                             a[mt][0].y, a[mt][1].y, b[nt].x, b[nt].y);
        }
        // epilogue: bias + relu (+ tf32 round & permute unless last layer)
        #pragma unroll
        for (int nt = 0; nt < NT; nt++) {
            int c0 = nbase + nt * 8 + 2 * r;
            float b0 = bias[c0], b1 = bias[c0 + 1];
            #pragma unroll
            for (int mt = 0; mt < 4; mt++) {
                int m0 = mt * 16 + q, m1 = m0 + 8;
                float v00 = fmaxf(acc[mt][nt][0] + b0, 0.f);
                float v01 = fmaxf(acc[mt][nt][1] + b1, 0.f);
                float v10 = fmaxf(acc[mt][nt][2] + b0, 0.f);
                float v11 = fmaxf(acc[mt][nt][3] + b1, 0.f);
                if (LASTL) {
                    Csh[m0 * CSTR + c0]     = v00;
                    Csh[m0 * CSTR + c0 + 1] = v01;
                    Csh[m1 * CSTR + c0]     = v10;
                    Csh[m1 * CSTR + c0 + 1] = v11;
                } else {
                    int s0 = slot8(c0), s1 = slot8(c0 + 1);
                    Csh[m0 * CSTR + s0] = tf32r(v00);
                    Csh[m0 * CSTR + s1] = tf32r(v01);
                    Csh[m1 * CSTR + s0] = tf32r(v10);
                    Csh[m1 * CSTR + s1] = tf32r(v11);
                }
            }
        }
    }
}

// ---------------- kernel 2: fused MLP + normalize + sums + current_prior ----------------
// shared (floats): bufB [64][520]=33280 (overlay bufF [64][132]),
//                  bufA [64][264]=16896, bufI [64][8]=512,
//                  sSum 2*13*128=3328, sInv 64, sLbl 64, sLab 64
#define SMEM_FLOATS (33280 + 16896 + 512 + 3328 + 64 + 64 + 64)

__global__ __launch_bounds__(NTHR, 1)
void mlp_kernel(const float* __restrict__ pos, const float* __restrict__ x,
                const int* __restrict__ y,
                const float* __restrict__ be1, const float* __restrict__ be2,
                const float* __restrict__ b1,  const float* __restrict__ b2,
                float* __restrict__ out, int P, int Npts)
{
    extern __shared__ float sm[];
    float* bufB = sm;                    // 33280
    float* bufA = bufB + 33280;          // 16896
    float* bufI = bufA + 16896;          // 512
    float* sSum = bufI + 512;            // 3328
    float* sInv = sSum + 3328;           // 64
    float* sLbl = sInv + 64;             // 64
    int*   sLab = (int*)(sLbl + 64);     // 64
    float* bufF = bufB;                  // overlay [64][132]

    const int tid  = threadIdx.x;
    const int lane = tid & 31, warp = tid >> 5;
    const int base = blockIdx.x * BM;

    // ---- load inputs into bufI [64][8] (permuted slots, tf32-rounded) ----
    for (int i = tid; i < BM * 8; i += NTHR) {
        int m = i >> 3, c = i & 7;
        int p = base + m;
        float v = 0.f;
        if (p < P && c < 7) {
            int b = p / Npts, n = p - b * Npts;
            if (c < 4) v = x[((size_t)b * 4 + c) * Npts + n];
            else       v = pos[(size_t)p * 3 + (c - 4)];
        }
        bufI[m * 8 + slot8(c)] = tf32r(v);
    }
    if (tid < BM) {
        int p = base + tid;
        int l = (p < P) ? y[p] : 0;
        sLab[tid] = l;
        float cnt = (float)g_counts[l];
        sLbl[tid] = (cnt >= MINPTS) ? (float)l : -1.f;
    }
    for (int i = tid; i < 2 * NCLS * PD; i += NTHR) sSum[i] = 0.f;
    __syncthreads();

    // ---- MLP chain (tf32 tensor cores) ----
    mma_layer<8,   256, 8,   264, 4, false>(g_wp + OFF1, be1, bufI, bufA, warp, lane);
    __syncthreads();
    mma_layer<256, 512, 264, 520, 4, false>(g_wp + OFF2, be2, bufA, bufB, warp, lane);
    __syncthreads();
    mma_layer<512, 256, 520, 264, 4, false>(g_wp + OFF3, b1,  bufB, bufA, warp, lane);
    __syncthreads();
    mma_layer<256, 128, 264, 132, 2, true >(g_wp + OFF4, b2,  bufA, bufF, warp, lane);
    __syncthreads();

    // ---- L2 norms ----
    if (tid < BM) {
        float s = 0.f;
        const float4* rr = (const float4*)(bufF + tid * 132);
        #pragma unroll
        for (int j = 0; j < 32; j++) {
            float4 qv = rr[j];
            s += qv.x * qv.x + qv.y * qv.y + qv.z * qv.z + qv.w * qv.w;
        }
        sInv[tid] = 1.f / fmaxf(sqrtf(s), 1e-12f);
    }
    __syncthreads();

    // ---- per-class sums (2 race-free shared copies) ----
    {
        int n = tid & 127, half = tid >> 7;
        float* dst = sSum + half * NCLS * PD + n;
        for (int mm = 0; mm < 32; mm++) {
            int m = (half << 5) + mm;
            if (base + m < P) {
                int l = sLab[m];
                dst[l * PD] += bufF[m * 132 + n] * sInv[m];
            }
        }
    }
    __syncthreads();
    for (int i = tid; i < NCLS * PD; i += NTHR)
        atomicAdd(&g_sums[i], sSum[i] + sSum[NCLS * PD + i]);

    // ---- write current_prior rows [64][129] ----
    size_t gbase = (size_t)base * 129;
    for (int i = tid; i < BM * 129; i += NTHR) {
        int m = i / 129, c = i - m * 129;
        if (base + m < P)
            out[gbase + i] = (c < PD) ? bufF[m * 132 + c] * sInv[m] : sLbl[m];
    }
}

// ---------------- kernel 3: EMA prior update (one warp per class) ----------------
__global__ void prior_kernel(const float* __restrict__ prior, float* __restrict__ out, int P) {
    int w = threadIdx.x >> 5;
    int lane = threadIdx.x & 31;
    if (w >= NCLS) return;
    float cnt = (float)g_counts[w];
    bool valid = (cnt >= MINPTS);
    float inv_cnt = 1.f / fmaxf(cnt, 1.f);
    float4 s4 = *(const float4*)&g_sums[w * PD + lane * 4];
    float4 p4 = *(const float4*)&prior[w * PD + lane * 4];
    float v[4];
    float pe[4] = {p4.x, p4.y, p4.z, p4.w};
    float mn[4] = {s4.x * inv_cnt, s4.y * inv_cnt, s4.z * inv_cnt, s4.w * inv_cnt};
    float ss = 0.f;
    #pragma unroll
    for (int i = 0; i < 4; i++) {
        float cur = valid ? mn[i] : pe[i];
        v[i] = 0.999f * pe[i] + 0.001f * cur;
        ss += v[i] * v[i];
    }
    #pragma unroll
    for (int o = 16; o > 0; o >>= 1) ss += __shfl_xor_sync(0xffffffffu, ss, o);
    float inv = 1.f / fmaxf(sqrtf(ss), 1e-12f);
    float4 ov = make_float4(v[0] * inv, v[1] * inv, v[2] * inv, v[3] * inv);
    *(float4*)&out[(size_t)P * 129 + w * PD + lane * 4] = ov;
}

// ---------------- launch ----------------
extern "C" void kernel_launch(void* const* d_in, const int* in_sizes, int n_in,
                              void* d_out, int out_size)
{
    const float* pos = (const float*)d_in[0];
    const float* x   = (const float*)d_in[1];
    const int*   y   = (const int*)  d_in[2];
    const float* We1 = (const float*)d_in[3];
    const float* be1 = (const float*)d_in[4];
    const float* We2 = (const float*)d_in[5];
    const float* be2 = (const float*)d_in[6];
    const float* W1  = (const float*)d_in[7];
    const float* b1  = (const float*)d_in[8];
    const float* W2  = (const float*)d_in[9];
    const float* b2  = (const float*)d_in[10];
    const float* pe  = (const float*)d_in[11];
    float* out = (float*)d_out;

    int P    = in_sizes[2];
    int B    = in_sizes[0] / 3 / 40000;
    int Npts = (B > 0) ? (in_sizes[0] / 3 / B) : 40000;

    size_t smem = SMEM_FLOATS * sizeof(float);
    cudaFuncSetAttribute(mlp_kernel, cudaFuncAttributeMaxDynamicSharedMemorySize, (int)smem);

    zero_kernel<<<7, 256>>>();
    count_kernel<<<(P + 255) / 256, 256>>>(y, P);
    pack_kernel<<<(8 * 256 + 255) / 256, 256>>>(We1, OFF1, 8, 256, 7);
    pack_kernel<<<(256 * 512 + 255) / 256, 256>>>(We2, OFF2, 256, 512, 256);
    pack_kernel<<<(512 * 256 + 255) / 256, 256>>>(W1, OFF3, 512, 256, 512);
    pack_kernel<<<(256 * 128 + 255) / 256, 256>>>(W2, OFF4, 256, 128, 256);
    mlp_kernel<<<(P + BM - 1) / BM, NTHR, smem>>>(pos, x, y, be1, be2, b1, b2,
                                                  out, P, Npts);
    prior_kernel<<<1, 416>>>(pe, out, P);
}

// round 3
// speedup vs baseline: 10.1393x; 2.0574x over previous
#include <cuda_runtime.h>
#include <cuda_fp16.h>
#include <cstdint>

#define NCLS   13
#define PD     128
#define BM     64
#define NTHR   256
#define MINPTS 256.0f

// packed fp16 weight offsets (K padded to mult of 16), element counts in halfs
#define OFF1 0                    // 16*256   = 4096
#define OFF2 4096                 // 256*512  = 131072
#define OFF3 (OFF2 + 131072)      // 512*256  = 131072
#define OFF4 (OFF3 + 131072)      // 256*128  = 32768
#define WPTOT (OFF4 + 32768)

__device__ __half g_wp[WPTOT];
__device__ float  g_sums[NCLS * PD];
__device__ int    g_counts[NCLS];

// ---- fp16 mma m16n8k16, f32 accumulate ----
__device__ __forceinline__ void mma_f16(float* c, uint32_t a0, uint32_t a1,
                                        uint32_t a2, uint32_t a3,
                                        uint32_t b0, uint32_t b1) {
    asm volatile(
        "mma.sync.aligned.m16n8k16.row.col.f32.f16.f16.f32 "
        "{%0,%1,%2,%3}, {%4,%5,%6,%7}, {%8,%9}, {%0,%1,%2,%3};\n"
        : "+f"(c[0]), "+f"(c[1]), "+f"(c[2]), "+f"(c[3])
        : "r"(a0), "r"(a1), "r"(a2), "r"(a3), "r"(b0), "r"(b1));
}

// column permutation within a 16-col k-group so (c, c+1, c+8, c+9) are one LDS.64
// slot(c) = pair*4 + hi*2 + low  where pair=(c&7)>>1, hi=c>>3, low=c&1
__device__ __forceinline__ int slot16(int c) {
    return (c & ~15) | ((c & 6) << 1) | ((c >> 2) & 2) | (c & 1);
}

// ---------------- kernel 0: zero scratch ----------------
__global__ void zero_kernel() {
    int i = blockIdx.x * blockDim.x + threadIdx.x;
    if (i < NCLS * PD) g_sums[i] = 0.f;
    if (i < NCLS) g_counts[i] = 0;
}

// ---------------- kernel 1: per-class counts ----------------
__global__ void count_kernel(const int* __restrict__ y, int P) {
    __shared__ int sc[NCLS];
    if (threadIdx.x < NCLS) sc[threadIdx.x] = 0;
    __syncthreads();
    for (int i = blockIdx.x * blockDim.x + threadIdx.x; i < P;
         i += gridDim.x * blockDim.x)
        atomicAdd(&sc[y[i]], 1);
    __syncthreads();
    if (threadIdx.x < NCLS) atomicAdd(&g_counts[threadIdx.x], sc[threadIdx.x]);
}

// ---------------- weight packing to fp16 fragment order ----------------
// 4 halfs per lane: [k0,k0+1,k0+8,k0+9] with k0 = kc*16 + 2r, n = j*8 + q
__device__ __forceinline__ void pack_one(const float* __restrict__ src,
                                         __half* __restrict__ dst,
                                         int p, int K, int N, int Ksrc) {
    int t = p & 3;
    int lane = (p >> 2) & 31;
    int rest = p >> 7;
    int kc = rest % (K >> 4);
    int j  = rest / (K >> 4);
    int r = lane & 3, q = lane >> 2;
    int k = kc * 16 + 2 * r + (t & 1) + 8 * (t >> 1);
    int n = j * 8 + q;
    float v = (k < Ksrc) ? src[k * N + n] : 0.f;
    dst[p] = __float2half(v);
}

__global__ void pack12_kernel(const float* __restrict__ We1,
                              const float* __restrict__ We2) {
    int p = blockIdx.x * blockDim.x + threadIdx.x;
    if (p < 4096)          pack_one(We1, g_wp + OFF1, p, 16, 256, 7);
    else if (p < 135168)   pack_one(We2, g_wp + OFF2, p - 4096, 256, 512, 256);
}
__global__ void pack3_kernel(const float* __restrict__ W1) {
    int p = blockIdx.x * blockDim.x + threadIdx.x;
    if (p < 131072) pack_one(W1, g_wp + OFF3, p, 512, 256, 512);
}
__global__ void pack4_kernel(const float* __restrict__ W2) {
    int p = blockIdx.x * blockDim.x + threadIdx.x;
    if (p < 32768) pack_one(W2, g_wp + OFF4, p, 256, 128, 256);
}

// ---------------- fp16 mma layer ----------------
// A in shared: row-major halfs [64][ASTR], slot16-permuted k-groups.
// W packed fp16 fragment order. Output: permuted halfs unless LASTL (f32, plain).
template <int K, int N, int ASTR, int CSTR, int NT, bool LASTL>
__device__ __forceinline__ void mma_layer(
    const __half* __restrict__ Wp, const float* __restrict__ bias,
    const __half* __restrict__ Ash, void* __restrict__ Cout,
    int warp, int lane)
{
    const int r = lane & 3, q = lane >> 2;
    constexpr int SLICE = N / 8;
    constexpr int NCH = SLICE / (NT * 8);
    #pragma unroll
    for (int ch = 0; ch < NCH; ch++) {
        const int nbase = warp * SLICE + ch * NT * 8;
        float acc[4][NT][4];
        #pragma unroll
        for (int mt = 0; mt < 4; mt++)
            #pragma unroll
            for (int nt = 0; nt < NT; nt++)
                #pragma unroll
                for (int i = 0; i < 4; i++) acc[mt][nt][i] = 0.f;

        #pragma unroll 4
        for (int kc = 0; kc < K / 16; kc++) {
            uint2 a[4][2];
            #pragma unroll
            for (int mt = 0; mt < 4; mt++) {
                a[mt][0] = *(const uint2*)&Ash[(mt * 16 + q)     * ASTR + kc * 16 + r * 4];
                a[mt][1] = *(const uint2*)&Ash[(mt * 16 + q + 8) * ASTR + kc * 16 + r * 4];
            }
            uint2 b[NT];
            #pragma unroll
            for (int nt = 0; nt < NT; nt++) {
                int j = (nbase >> 3) + nt;
                b[nt] = *(const uint2*)&Wp[(size_t)((j * (K / 16) + kc) * 32 + lane) * 4];
            }
            #pragma unroll
            for (int mt = 0; mt < 4; mt++)
                #pragma unroll
                for (int nt = 0; nt < NT; nt++)
                    mma_f16(acc[mt][nt], a[mt][0].x, a[mt][1].x,
                            a[mt][0].y, a[mt][1].y, b[nt].x, b[nt].y);
        }
        // epilogue: bias + relu
        #pragma unroll
        for (int nt = 0; nt < NT; nt++) {
            int c0 = nbase + nt * 8 + 2 * r;
            float b0 = bias[c0], b1 = bias[c0 + 1];
            #pragma unroll
            for (int mt = 0; mt < 4; mt++) {
                int m0 = mt * 16 + q, m1 = m0 + 8;
                float v00 = fmaxf(acc[mt][nt][0] + b0, 0.f);
                float v01 = fmaxf(acc[mt][nt][1] + b1, 0.f);
                float v10 = fmaxf(acc[mt][nt][2] + b0, 0.f);
                float v11 = fmaxf(acc[mt][nt][3] + b1, 0.f);
                if (LASTL) {
                    float* C = (float*)Cout;
                    *(float2*)&C[m0 * CSTR + c0] = make_float2(v00, v01);
                    *(float2*)&C[m1 * CSTR + c0] = make_float2(v10, v11);
                } else {
                    __half* C = (__half*)Cout;
                    int s = slot16(c0);       // even -> half2 aligned
                    *(__half2*)&C[m0 * CSTR + s] = __floats2half2_rn(v00, v01);
                    *(__half2*)&C[m1 * CSTR + s] = __floats2half2_rn(v10, v11);
                }
            }
        }
    }
}

// ---------------- kernel: fused MLP + normalize + sums + current_prior ----------------
// smem bytes: bufB_h 64*528*2=67584 (overlay bufF f32 64*132*4=33792)
//             bufA_h 64*272*2=34816 (overlay sSum 2*13*128*4=13312 after layer4)
//             bufI_h 64*16*2=2048,  extras 768
#define SMEM_BYTES (67584 + 34816 + 2048 + 768)

__global__ __launch_bounds__(NTHR, 2)
void mlp_kernel(const float* __restrict__ pos, const float* __restrict__ x,
                const int* __restrict__ y,
                const float* __restrict__ be1, const float* __restrict__ be2,
                const float* __restrict__ b1,  const float* __restrict__ b2,
                float* __restrict__ out, int P, int Npts)
{
    extern __shared__ __align__(16) char smraw[];
    __half* bufB = (__half*)smraw;                      // [64][528]
    __half* bufA = (__half*)(smraw + 67584);            // [64][272]
    __half* bufI = (__half*)(smraw + 67584 + 34816);    // [64][16]
    float*  sInv = (float*)(smraw + 67584 + 34816 + 2048);   // 64
    float*  sLbl = sInv + 64;                           // 64
    int*    sLab = (int*)(sLbl + 64);                   // 64
    float*  bufF = (float*)smraw;                       // overlay [64][132]
    float*  sSum = (float*)(smraw + 67584);             // overlay 2*13*128

    const int tid  = threadIdx.x;
    const int lane = tid & 31, warp = tid >> 5;
    const int base = blockIdx.x * BM;

    // ---- load inputs into bufI [64][16] (permuted slots, fp16) ----
    for (int i = tid; i < BM * 16; i += NTHR) {
        int m = i >> 4, c = i & 15;
        int p = base + m;
        float v = 0.f;
        if (p < P && c < 7) {
            int b = p / Npts, n = p - b * Npts;
            if (c < 4) v = x[((size_t)b * 4 + c) * Npts + n];
            else       v = pos[(size_t)p * 3 + (c - 4)];
        }
        bufI[m * 16 + slot16(c)] = __float2half(v);
    }
    if (tid < BM) {
        int p = base + tid;
        int l = (p < P) ? y[p] : 0;
        sLab[tid] = l;
        float cnt = (float)g_counts[l];
        sLbl[tid] = (cnt >= MINPTS) ? (float)l : -1.f;
    }
    __syncthreads();

    // ---- MLP chain (fp16 tensor cores, f32 accumulate) ----
    mma_layer<16,  256, 16,  272, 4, false>(g_wp + OFF1, be1, bufI, bufA, warp, lane);
    __syncthreads();
    mma_layer<256, 512, 272, 528, 4, false>(g_wp + OFF2, be2, bufA, bufB, warp, lane);
    __syncthreads();
    mma_layer<512, 256, 528, 272, 4, false>(g_wp + OFF3, b1,  bufB, bufA, warp, lane);
    __syncthreads();
    mma_layer<256, 128, 272, 132, 2, true >(g_wp + OFF4, b2,  bufA, bufF, warp, lane);
    __syncthreads();

    // ---- zero sum overlay (bufA dead now) + L2 norms ----
    for (int i = tid; i < 2 * NCLS * PD; i += NTHR) sSum[i] = 0.f;
    if (tid < BM) {
        float s = 0.f;
        const float4* rr = (const float4*)(bufF + tid * 132);
        #pragma unroll
        for (int j = 0; j < 32; j++) {
            float4 qv = rr[j];
            s += qv.x * qv.x + qv.y * qv.y + qv.z * qv.z + qv.w * qv.w;
        }
        sInv[tid] = 1.f / fmaxf(sqrtf(s), 1e-12f);
    }
    __syncthreads();

    // ---- per-class sums (2 race-free shared copies) ----
    {
        int n = tid & 127, half = tid >> 7;
        float* dst = sSum + half * NCLS * PD + n;
        for (int mm = 0; mm < 32; mm++) {
            int m = (half << 5) + mm;
            if (base + m < P) {
                int l = sLab[m];
                dst[l * PD] += bufF[m * 132 + n] * sInv[m];
            }
        }
    }
    __syncthreads();
    for (int i = tid; i < NCLS * PD; i += NTHR)
        atomicAdd(&g_sums[i], sSum[i] + sSum[NCLS * PD + i]);

    // ---- write current_prior rows [64][129] ----
    size_t gbase = (size_t)base * 129;
    for (int i = tid; i < BM * 129; i += NTHR) {
        int m = i / 129, c = i - m * 129;
        if (base + m < P)
            out[gbase + i] = (c < PD) ? bufF[m * 132 + c] * sInv[m] : sLbl[m];
    }
}

// ---------------- kernel: EMA prior update (one warp per class) ----------------
__global__ void prior_kernel(const float* __restrict__ prior, float* __restrict__ out, int P) {
    int w = threadIdx.x >> 5;
    int lane = threadIdx.x & 31;
    if (w >= NCLS) return;
    float cnt = (float)g_counts[w];
    bool valid = (cnt >= MINPTS);
    float inv_cnt = 1.f / fmaxf(cnt, 1.f);
    float4 s4 = *(const float4*)&g_sums[w * PD + lane * 4];
    float4 p4 = *(const float4*)&prior[w * PD + lane * 4];
    float v[4];
    float pe[4] = {p4.x, p4.y, p4.z, p4.w};
    float mn[4] = {s4.x * inv_cnt, s4.y * inv_cnt, s4.z * inv_cnt, s4.w * inv_cnt};
    float ss = 0.f;
    #pragma unroll
    for (int i = 0; i < 4; i++) {
        float cur = valid ? mn[i] : pe[i];
        v[i] = 0.999f * pe[i] + 0.001f * cur;
        ss += v[i] * v[i];
    }
    #pragma unroll
    for (int o = 16; o > 0; o >>= 1) ss += __shfl_xor_sync(0xffffffffu, ss, o);
    float inv = 1.f / fmaxf(sqrtf(ss), 1e-12f);
    float4 ov = make_float4(v[0] * inv, v[1] * inv, v[2] * inv, v[3] * inv);
    *(float4*)&out[(size_t)P * 129 + w * PD + lane * 4] = ov;
}

// ---------------- launch (mlp is launch index 5 for ncu -s 5 -c 1) ----------------
extern "C" void kernel_launch(void* const* d_in, const int* in_sizes, int n_in,
                              void* d_out, int out_size)
{
    const float* pos = (const float*)d_in[0];
    const float* x   = (const float*)d_in[1];
    const int*   y   = (const int*)  d_in[2];
    const float* We1 = (const float*)d_in[3];
    const float* be1 = (const float*)d_in[4];
    const float* We2 = (const float*)d_in[5];
    const float* be2 = (const float*)d_in[6];
    const float* W1  = (const float*)d_in[7];
    const float* b1  = (const float*)d_in[8];
    const float* W2  = (const float*)d_in[9];
    const float* b2  = (const float*)d_in[10];
    const float* pe  = (const float*)d_in[11];
    float* out = (float*)d_out;

    int P    = in_sizes[2];
    int B    = in_sizes[0] / 3 / 40000;
    int Npts = (B > 0) ? (in_sizes[0] / 3 / B) : 40000;

    cudaFuncSetAttribute(mlp_kernel, cudaFuncAttributeMaxDynamicSharedMemorySize, SMEM_BYTES);

    zero_kernel<<<7, 256>>>();                               // 0
    count_kernel<<<(P + 255) / 256, 256>>>(y, P);            // 1
    pack12_kernel<<<(135168 + 255) / 256, 256>>>(We1, We2);  // 2
    pack3_kernel<<<(131072 + 255) / 256, 256>>>(W1);         // 3
    pack4_kernel<<<(32768 + 255) / 256, 256>>>(W2);          // 4
    mlp_kernel<<<(P + BM - 1) / BM, NTHR, SMEM_BYTES>>>(pos, x, y, be1, be2,
                                                        b1, b2, out, P, Npts); // 5
    prior_kernel<<<1, 416>>>(pe, out, P);                    // 6
}